// round 3
// baseline (speedup 1.0000x reference)
#include <cuda_runtime.h>
#include <cuda_bf16.h>
#include <cstddef>

// Problem dims
#define B_  64
#define S_  512
#define T_  64
#define H_  512
#define D_  512
#define G_  1536   // 3*H

// ---------------- scratch (static device allocations) ----------------
__device__ float g_gi_pre [B_ * S_ * G_];     // 201 MB
__device__ float g_gi_post[B_ * S_ * G_];     // 201 MB
__device__ float g_gi_dec [B_ * T_ * G_];     // 25 MB
__device__ float g_WT_pre [D_ * G_];          // Wih transposed: [D][3H]
__device__ float g_WT_post[D_ * G_];
__device__ float g_WT_dec [D_ * G_];
__device__ float g_states_pre [S_ * B_ * H_]; // h after each step, [t][b][h]
__device__ float g_states_post[S_ * B_ * H_];
__device__ float g_dstates    [T_ * B_ * H_];
__device__ float g_dec_h0 [B_ * H_];
__device__ float g_score  [B_ * 2 * S_];      // score_enc[b][col], col in [0,1024)
__device__ float g_hscore [B_ * T_];
__device__ int   g_dec_tokens[B_ * T_];

// ---------------- helpers ----------------
__device__ __forceinline__ float fast_sigmoid(float x) {
    return 1.0f / (1.0f + __expf(-x));
}

__device__ __forceinline__ float blockReduce128(float v) {
    __shared__ float red[4];
    #pragma unroll
    for (int o = 16; o; o >>= 1) v += __shfl_xor_sync(0xffffffffu, v, o);
    if ((threadIdx.x & 31) == 0) red[threadIdx.x >> 5] = v;
    __syncthreads();
    if (threadIdx.x == 0) v = red[0] + red[1] + red[2] + red[3];
    return v;
}

// ---------------- 1. transpose Wih (1536 x 512) -> WT (512 x 1536) ----------------
__global__ void transpose_k(const float* __restrict__ src, float* __restrict__ dst) {
    // src: R=1536 rows, C=512 cols.  dst: C rows, R cols.
    __shared__ float tile[32][33];
    int x = blockIdx.x * 32 + threadIdx.x;   // col in src (< 512)
    int y = blockIdx.y * 32 + threadIdx.y;   // row in src (< 1536)
    #pragma unroll
    for (int i = 0; i < 32; i += 8)
        tile[threadIdx.y + i][threadIdx.x] = src[(size_t)(y + i) * D_ + x];
    __syncthreads();
    int x2 = blockIdx.y * 32 + threadIdx.x;  // col in dst (< 1536)
    int y2 = blockIdx.x * 32 + threadIdx.y;  // row in dst (< 512)
    #pragma unroll
    for (int i = 0; i < 32; i += 8)
        dst[(size_t)(y2 + i) * G_ + x2] = tile[threadIdx.x][threadIdx.y + i];
}

// ---------------- 2. build decoder tokens ----------------
__global__ void dec_tokens_kernel(const int* __restrict__ pre_seq, const int* __restrict__ trg) {
    int idx = blockIdx.x * blockDim.x + threadIdx.x;
    if (idx >= B_ * T_) return;
    int b = idx >> 6;
    int t = idx & 63;
    g_dec_tokens[idx] = (t == 0) ? pre_seq[b * S_ + (S_ - 1)] : trg[b * T_ + t - 1];
}

// ---------------- 3. gi GEMM: out[m,g] = sum_d emb[tok[m],d] * WT[d,g] + bias[g] ----------------
// BM=128, BN=128, BK=8, 256 threads, 8x8 per thread
__global__ void gi_gemm(const int* __restrict__ tokens,
                        const float* __restrict__ emb,
                        const float* __restrict__ WT,     // D_ x G_
                        const float* __restrict__ bias,   // G_
                        float* __restrict__ out) {
    __shared__ float As[8][128];
    __shared__ float Bs[8][128];
    int tid  = threadIdx.x;
    int row0 = blockIdx.y * 128;
    int col0 = blockIdx.x * 128;

    int ar = tid >> 1;
    int ac = (tid & 1) * 4;
    int token = tokens[row0 + ar];
    const float* arow = emb + (size_t)token * D_ + ac;

    int br = tid >> 5;
    int bc = (tid & 31) * 4;
    const float* bptr = WT + (size_t)br * G_ + col0 + bc;

    int tr = (tid >> 4) * 8;
    int tc = (tid & 15) * 8;

    float acc[8][8];
    #pragma unroll
    for (int i = 0; i < 8; i++)
        #pragma unroll
        for (int j = 0; j < 8; j++) acc[i][j] = 0.0f;

    for (int k0 = 0; k0 < D_; k0 += 8) {
        float4 av = *(const float4*)(arow + k0);
        As[ac + 0][ar] = av.x; As[ac + 1][ar] = av.y;
        As[ac + 2][ar] = av.z; As[ac + 3][ar] = av.w;
        float4 bv = *(const float4*)(bptr + (size_t)k0 * G_);
        *(float4*)&Bs[br][bc] = bv;
        __syncthreads();
        #pragma unroll
        for (int k = 0; k < 8; k++) {
            float a[8], bb[8];
            *(float4*)(a)      = *(const float4*)&As[k][tr];
            *(float4*)(a + 4)  = *(const float4*)&As[k][tr + 4];
            *(float4*)(bb)     = *(const float4*)&Bs[k][tc];
            *(float4*)(bb + 4) = *(const float4*)&Bs[k][tc + 4];
            #pragma unroll
            for (int i = 0; i < 8; i++)
                #pragma unroll
                for (int j = 0; j < 8; j++)
                    acc[i][j] = fmaf(a[i], bb[j], acc[i][j]);
        }
        __syncthreads();
    }

    #pragma unroll
    for (int i = 0; i < 8; i++) {
        #pragma unroll
        for (int j = 0; j < 8; j += 4) {
            float4 v;
            v.x = acc[i][j + 0] + bias[col0 + tc + j + 0];
            v.y = acc[i][j + 1] + bias[col0 + tc + j + 1];
            v.z = acc[i][j + 2] + bias[col0 + tc + j + 2];
            v.w = acc[i][j + 3] + bias[col0 + tc + j + 3];
            *(float4*)&out[(size_t)(row0 + tr + i) * G_ + col0 + tc + j] = v;
        }
    }
}

// ---------------- 4. GRU step kernel (one timestep) ----------------
struct StepArgs {
    const float* h_prev;   // B_ x H_, or nullptr => zeros
    const float* gi_t;     // gi element (b): gi_t[b*gi_bstride + gate*H_ + j]
    const float* Whh;      // G_ x H_ row-major
    const float* bhh;      // G_
    float*       h_out;    // B_ x H_
};

// grid: (H_/8, nGRU), 256 threads (8 warps, 1 hidden unit per warp)
// dyn smem: 64*512 floats (h) + 8*64*3 floats (reduced gates)
#define STEP_SMEM (B_ * H_ * 4 + 8 * B_ * 3 * 4)

__global__ void gru_step(StepArgs a0, StepArgs a1, int gi_bstride) {
    StepArgs a = (blockIdx.y == 0) ? a0 : a1;
    extern __shared__ float sm[];
    float* hs = sm;                 // [64][512]
    float* gh = sm + B_ * H_;       // [8][64][3]

    int tid  = threadIdx.x;
    int lane = tid & 31;
    int w    = tid >> 5;
    int j    = blockIdx.x * 8 + w;

    // per-lane weight slices (row-major rows of Whh, coalesced loads)
    const float* Wr = a.Whh + (size_t)(0 * H_ + j) * H_;
    const float* Wz = a.Whh + (size_t)(1 * H_ + j) * H_;
    const float* Wn = a.Whh + (size_t)(2 * H_ + j) * H_;
    float wr[16], wz[16], wn[16];
    #pragma unroll
    for (int i = 0; i < 16; i++) {
        wr[i] = Wr[lane + 32 * i];
        wz[i] = Wz[lane + 32 * i];
        wn[i] = Wn[lane + 32 * i];
    }

    // load h_prev (or zeros) into smem
    {
        float4* dst = (float4*)hs;
        if (a.h_prev) {
            const float4* src = (const float4*)a.h_prev;
            for (int i = tid; i < B_ * H_ / 4; i += 256) dst[i] = src[i];
        } else {
            float4 z = make_float4(0.f, 0.f, 0.f, 0.f);
            for (int i = tid; i < B_ * H_ / 4; i += 256) dst[i] = z;
        }
    }
    __syncthreads();

    // dot products: per warp, for each batch row b, three length-512 dots
    for (int b = 0; b < B_; b++) {
        const float* hb = hs + b * H_;
        float pr = 0.f, pz = 0.f, pn = 0.f;
        #pragma unroll
        for (int i = 0; i < 16; i++) {
            float hv = hb[lane + 32 * i];
            pr = fmaf(hv, wr[i], pr);
            pz = fmaf(hv, wz[i], pz);
            pn = fmaf(hv, wn[i], pn);
        }
        #pragma unroll
        for (int o = 16; o; o >>= 1) {
            pr += __shfl_xor_sync(0xffffffffu, pr, o);
            pz += __shfl_xor_sync(0xffffffffu, pz, o);
            pn += __shfl_xor_sync(0xffffffffu, pn, o);
        }
        if (lane == 0) {
            float* g = gh + (w * B_ + b) * 3;
            g[0] = pr; g[1] = pz; g[2] = pn;
        }
    }
    __syncwarp();

    // gate math: each lane handles 2 batch rows for its warp's hidden unit j
    float br_ = a.bhh[j], bz_ = a.bhh[H_ + j], bn_ = a.bhh[2 * H_ + j];
    #pragma unroll
    for (int q = 0; q < 2; q++) {
        int b = lane + 32 * q;
        const float* g = gh + (w * B_ + b) * 3;
        float hr = g[0] + br_;
        float hz = g[1] + bz_;
        float hn = g[2] + bn_;
        const float* gi = a.gi_t + (size_t)b * gi_bstride;
        float ir  = gi[j];
        float iz  = gi[H_ + j];
        float inn = gi[2 * H_ + j];
        float r = fast_sigmoid(ir + hr);
        float z = fast_sigmoid(iz + hz);
        float n = tanhf(inn + r * hn);
        float hprev = hs[b * H_ + j];
        a.h_out[b * H_ + j] = (1.0f - z) * n + z * hprev;
    }
}

// ---------------- 5. enc_hidden -> decoder h0 ----------------
// grid (512, 64), 128 threads: dec_h0[b][j] = tanh( [pre_h,post_h] . enc_fc_w[j,:] + b[j] )
__global__ void enc_hidden_kernel(const float* __restrict__ enc_fc_w,
                                  const float* __restrict__ enc_fc_b) {
    int j = blockIdx.x, b = blockIdx.y;
    const float* hp = g_states_pre  + ((size_t)(S_ - 1) * B_ + b) * H_;
    const float* hq = g_states_post + ((size_t)(S_ - 1) * B_ + b) * H_;
    const float* wrow = enc_fc_w + (size_t)j * (2 * H_);
    float acc = 0.f;
    for (int k = threadIdx.x; k < H_; k += 128)
        acc += hp[k] * wrow[k] + hq[k] * wrow[H_ + k];
    acc = blockReduce128(acc);
    if (threadIdx.x == 0) g_dec_h0[b * H_ + j] = tanhf(acc + enc_fc_b[j]);
}

// ---------------- 6. score_enc ----------------
// grid (1024, 64), 128 threads: score[b][c] = relu(states[e][t][b][:]) . w_enc
__global__ void score_enc_kernel(const float* __restrict__ out_w) {
    int c = blockIdx.x, b = blockIdx.y;
    int e = c >> 9, t = c & (S_ - 1);
    const float* src = (e ? g_states_post : g_states_pre) + ((size_t)t * B_ + b) * H_;
    float acc = 0.f;
    for (int h = threadIdx.x; h < H_; h += 128)
        acc += fmaxf(src[h], 0.f) * out_w[h];
    acc = blockReduce128(acc);
    if (threadIdx.x == 0) g_score[b * (2 * S_) + c] = acc;
}

// ---------------- 7. hscore ----------------
// grid (64, 64), 128 threads: hscore[b][t] = relu(dstates[t][b][:]) . w_hid + out_b
__global__ void hscore_kernel(const float* __restrict__ out_w, const float* __restrict__ out_b) {
    int t = blockIdx.x, b = blockIdx.y;
    const float* src = g_dstates + ((size_t)t * B_ + b) * H_;
    float acc = 0.f;
    for (int h = threadIdx.x; h < H_; h += 128)
        acc += fmaxf(src[h], 0.f) * out_w[H_ + h];
    acc = blockReduce128(acc);
    if (threadIdx.x == 0) g_hscore[b * T_ + t] = acc + out_b[0];
}

// ---------------- 8. final output: sigmoid fill ----------------
// out[p*B*T*S + b*T*S + t*S + s] = sigmoid(score[b][p*512+s] + hscore[b][t])
__global__ void output_kernel(float* __restrict__ out) {
    int idx = blockIdx.x * blockDim.x + threadIdx.x;   // < 4194304
    int p  = idx >> 21;
    int r  = idx & ((1 << 21) - 1);
    int b  = r >> 15;
    int r2 = r & 32767;
    int t  = r2 >> 9;
    int s  = r2 & 511;
    float logit = g_score[b * (2 * S_) + p * S_ + s] + g_hscore[b * T_ + t];
    out[idx] = fast_sigmoid(logit);
}

// ---------------- host ----------------
extern "C" void kernel_launch(void* const* d_in, const int* in_sizes, int n_in,
                              void* d_out, int out_size) {
    const int*   pre_seq   = (const int*)  d_in[0];
    const int*   post_seq  = (const int*)  d_in[1];
    const int*   trg       = (const int*)  d_in[2];
    const float* emb       = (const float*)d_in[3];
    const float* pre_Wih   = (const float*)d_in[4];
    const float* pre_Whh   = (const float*)d_in[5];
    const float* pre_bih   = (const float*)d_in[6];
    const float* pre_bhh   = (const float*)d_in[7];
    const float* post_Wih  = (const float*)d_in[8];
    const float* post_Whh  = (const float*)d_in[9];
    const float* post_bih  = (const float*)d_in[10];
    const float* post_bhh  = (const float*)d_in[11];
    const float* enc_fc_w  = (const float*)d_in[12];
    const float* enc_fc_b  = (const float*)d_in[13];
    const float* dec_Wih   = (const float*)d_in[14];
    const float* dec_Whh   = (const float*)d_in[15];
    const float* dec_bih   = (const float*)d_in[16];
    const float* dec_bhh   = (const float*)d_in[17];
    const float* out_w     = (const float*)d_in[18];
    const float* out_b     = (const float*)d_in[19];
    float* out = (float*)d_out;

    float *gi_pre, *gi_post, *gi_dec, *wt_pre, *wt_post, *wt_dec;
    float *st_pre, *st_post, *dst, *dec_h0;
    int* dec_tok;
    cudaGetSymbolAddress((void**)&gi_pre,  g_gi_pre);
    cudaGetSymbolAddress((void**)&gi_post, g_gi_post);
    cudaGetSymbolAddress((void**)&gi_dec,  g_gi_dec);
    cudaGetSymbolAddress((void**)&wt_pre,  g_WT_pre);
    cudaGetSymbolAddress((void**)&wt_post, g_WT_post);
    cudaGetSymbolAddress((void**)&wt_dec,  g_WT_dec);
    cudaGetSymbolAddress((void**)&st_pre,  g_states_pre);
    cudaGetSymbolAddress((void**)&st_post, g_states_post);
    cudaGetSymbolAddress((void**)&dst,     g_dstates);
    cudaGetSymbolAddress((void**)&dec_h0,  g_dec_h0);
    cudaGetSymbolAddress((void**)&dec_tok, g_dec_tokens);

    cudaFuncSetAttribute(gru_step, cudaFuncAttributeMaxDynamicSharedMemorySize, STEP_SMEM);

    dim3 tb(32, 8);
    transpose_k<<<dim3(16, 48), tb>>>(pre_Wih,  wt_pre);
    transpose_k<<<dim3(16, 48), tb>>>(post_Wih, wt_post);
    transpose_k<<<dim3(16, 48), tb>>>(dec_Wih,  wt_dec);

    dec_tokens_kernel<<<16, 256>>>(pre_seq, trg);

    gi_gemm<<<dim3(12, 256), 256>>>(pre_seq,  emb, wt_pre,  pre_bih,  gi_pre);
    gi_gemm<<<dim3(12, 256), 256>>>(post_seq, emb, wt_post, post_bih, gi_post);
    gi_gemm<<<dim3(12, 32),  256>>>(dec_tok,  emb, wt_dec,  dec_bih,  gi_dec);

    // encoder recurrence: 512 steps, both GRUs per launch
    for (int t = 0; t < S_; t++) {
        StepArgs a0, a1;
        a0.h_prev = (t == 0) ? nullptr : st_pre + (size_t)(t - 1) * B_ * H_;
        a0.gi_t   = gi_pre + (size_t)t * G_;
        a0.Whh    = pre_Whh;  a0.bhh = pre_bhh;
        a0.h_out  = st_pre + (size_t)t * B_ * H_;
        a1.h_prev = (t == 0) ? nullptr : st_post + (size_t)(t - 1) * B_ * H_;
        a1.gi_t   = gi_post + (size_t)t * G_;
        a1.Whh    = post_Whh; a1.bhh = post_bhh;
        a1.h_out  = st_post + (size_t)t * B_ * H_;
        gru_step<<<dim3(H_ / 8, 2), 256, STEP_SMEM>>>(a0, a1, S_ * G_);
    }

    enc_hidden_kernel<<<dim3(H_, B_), 128>>>(enc_fc_w, enc_fc_b);
    score_enc_kernel<<<dim3(2 * S_, B_), 128>>>(out_w);

    // decoder recurrence: 64 steps
    for (int t = 0; t < T_; t++) {
        StepArgs a0;
        a0.h_prev = (t == 0) ? dec_h0 : dst + (size_t)(t - 1) * B_ * H_;
        a0.gi_t   = gi_dec + (size_t)t * G_;
        a0.Whh    = dec_Whh;  a0.bhh = dec_bhh;
        a0.h_out  = dst + (size_t)t * B_ * H_;
        gru_step<<<dim3(H_ / 8, 1), 256, STEP_SMEM>>>(a0, a0, T_ * G_);
    }

    hscore_kernel<<<dim3(T_, B_), 128>>>(out_w, out_b);
    output_kernel<<<(2 * B_ * T_ * S_) / 256, 256>>>(out);
}

// round 4
// speedup vs baseline: 1.3576x; 1.3576x over previous
#include <cuda_runtime.h>
#include <cuda_bf16.h>
#include <cstdint>
#include <cstddef>

// Problem dims
#define B_  64
#define S_  512
#define T_  64
#define H_  512
#define D_  512
#define G_  1536   // 3*H

// ---------------- scratch (static device allocations) ----------------
__device__ float g_gi_pre [B_ * S_ * G_];     // 201 MB
__device__ float g_gi_post[B_ * S_ * G_];     // 201 MB
__device__ float g_gi_dec [B_ * T_ * G_];     // 25 MB
__device__ float g_WT_pre [D_ * G_];          // Wih transposed: [D][3H]
__device__ float g_WT_post[D_ * G_];
__device__ float g_WT_dec [D_ * G_];
__device__ float g_states_pre [S_ * B_ * H_]; // h after each step, [t][b][h]
__device__ float g_states_post[S_ * B_ * H_];
__device__ float g_dstates    [T_ * B_ * H_];
__device__ float g_dec_h0 [B_ * H_];
__device__ float g_score  [B_ * 2 * S_];      // score_enc[b][col], col in [0,1024)
__device__ float g_hscore [B_ * T_];
__device__ int   g_dec_tokens[B_ * T_];

// ---------------- helpers ----------------
__device__ __forceinline__ float fast_sigmoid(float x) {
    return 1.0f / (1.0f + __expf(-x));
}

__device__ __forceinline__ float blockReduce128(float v) {
    __shared__ float red[4];
    #pragma unroll
    for (int o = 16; o; o >>= 1) v += __shfl_xor_sync(0xffffffffu, v, o);
    if ((threadIdx.x & 31) == 0) red[threadIdx.x >> 5] = v;
    __syncthreads();
    if (threadIdx.x == 0) v = red[0] + red[1] + red[2] + red[3];
    return v;
}

// ---------------- 1. transpose Wih (1536 x 512) -> WT (512 x 1536) ----------------
__global__ void transpose_k(const float* __restrict__ src, float* __restrict__ dst) {
    __shared__ float tile[32][33];
    int x = blockIdx.x * 32 + threadIdx.x;   // col in src (< 512)
    int y = blockIdx.y * 32 + threadIdx.y;   // row in src (< 1536)
    #pragma unroll
    for (int i = 0; i < 32; i += 8)
        tile[threadIdx.y + i][threadIdx.x] = src[(size_t)(y + i) * D_ + x];
    __syncthreads();
    int x2 = blockIdx.y * 32 + threadIdx.x;  // col in dst (< 1536)
    int y2 = blockIdx.x * 32 + threadIdx.y;  // row in dst (< 512)
    #pragma unroll
    for (int i = 0; i < 32; i += 8)
        dst[(size_t)(y2 + i) * G_ + x2] = tile[threadIdx.x][threadIdx.y + i];
}

// ---------------- 2. build decoder tokens ----------------
__global__ void dec_tokens_kernel(const int* __restrict__ pre_seq, const int* __restrict__ trg) {
    int idx = blockIdx.x * blockDim.x + threadIdx.x;
    if (idx >= B_ * T_) return;
    int b = idx >> 6;
    int t = idx & 63;
    g_dec_tokens[idx] = (t == 0) ? pre_seq[b * S_ + (S_ - 1)] : trg[b * T_ + t - 1];
}

// ---------------- 3. gi GEMM (128x128x8 tiles, 256 thr, 8x8/thread) ----------------
__global__ void gi_gemm(const int* __restrict__ tokens,
                        const float* __restrict__ emb,
                        const float* __restrict__ WT,     // D_ x G_
                        const float* __restrict__ bias,   // G_
                        float* __restrict__ out) {
    __shared__ float As[8][128];
    __shared__ float Bs[8][128];
    int tid  = threadIdx.x;
    int row0 = blockIdx.y * 128;
    int col0 = blockIdx.x * 128;

    int ar = tid >> 1;
    int ac = (tid & 1) * 4;
    int token = tokens[row0 + ar];
    const float* arow = emb + (size_t)token * D_ + ac;

    int br = tid >> 5;
    int bc = (tid & 31) * 4;
    const float* bptr = WT + (size_t)br * G_ + col0 + bc;

    int tr = (tid >> 4) * 8;
    int tc = (tid & 15) * 8;

    float acc[8][8];
    #pragma unroll
    for (int i = 0; i < 8; i++)
        #pragma unroll
        for (int j = 0; j < 8; j++) acc[i][j] = 0.0f;

    for (int k0 = 0; k0 < D_; k0 += 8) {
        float4 av = *(const float4*)(arow + k0);
        As[ac + 0][ar] = av.x; As[ac + 1][ar] = av.y;
        As[ac + 2][ar] = av.z; As[ac + 3][ar] = av.w;
        float4 bv = *(const float4*)(bptr + (size_t)k0 * G_);
        *(float4*)&Bs[br][bc] = bv;
        __syncthreads();
        #pragma unroll
        for (int k = 0; k < 8; k++) {
            float a[8], bb[8];
            *(float4*)(a)      = *(const float4*)&As[k][tr];
            *(float4*)(a + 4)  = *(const float4*)&As[k][tr + 4];
            *(float4*)(bb)     = *(const float4*)&Bs[k][tc];
            *(float4*)(bb + 4) = *(const float4*)&Bs[k][tc + 4];
            #pragma unroll
            for (int i = 0; i < 8; i++)
                #pragma unroll
                for (int j = 0; j < 8; j++)
                    acc[i][j] = fmaf(a[i], bb[j], acc[i][j]);
        }
        __syncthreads();
    }

    #pragma unroll
    for (int i = 0; i < 8; i++) {
        #pragma unroll
        for (int j = 0; j < 8; j += 4) {
            float4 v;
            v.x = acc[i][j + 0] + bias[col0 + tc + j + 0];
            v.y = acc[i][j + 1] + bias[col0 + tc + j + 1];
            v.z = acc[i][j + 2] + bias[col0 + tc + j + 2];
            v.w = acc[i][j + 3] + bias[col0 + tc + j + 3];
            *(float4*)&out[(size_t)(row0 + tr + i) * G_ + col0 + tc + j] = v;
        }
    }
}

// ---------------- 4. GRU step kernel (one timestep) ----------------
struct StepArgs {
    const float* h_prev;   // B_ x H_, or nullptr => zeros
    const float* gi_t;     // gi_t[b*gi_bstride + gate*H_ + j]
    const float* Whh;      // G_ x H_ row-major
    const float* bhh;      // G_
    float*       h_out;    // B_ x H_
};

// Shuffle-free packed-SIMD step:
//   grid (H_/8, nGRU), 256 threads.
//   thread (j = tx&7, b0 = tx>>3): computes r,z,n for (b0, j) and (b0+32, j)
//   K runs sequentially per thread, 2-wide SIMD over (k,k+1) via fma.rn.f32x2.
//   smem: h [64][516] + W [24][516], pitch 516 -> conflict-free, 16B aligned.
#define PH_ 516
#define STEP_SMEM ((B_ * PH_ + 24 * PH_) * 4)   // 181,632 B

__device__ __forceinline__ float pk_lo(unsigned long long p) {
    return __uint_as_float((unsigned)(p & 0xffffffffull));
}
__device__ __forceinline__ float pk_hi(unsigned long long p) {
    return __uint_as_float((unsigned)(p >> 32));
}

__global__ void gru_step(StepArgs a0, StepArgs a1, int gi_bstride) {
    StepArgs a = (blockIdx.y == 0) ? a0 : a1;
    extern __shared__ float sm[];
    float* hs  = sm;                 // [64][PH_]
    float* wsm = sm + B_ * PH_;      // [24][PH_]  rows: gate*8 + j_local

    int tid = threadIdx.x;
    int jl  = tid & 7;
    int b0  = tid >> 3;              // 0..31
    int jg  = blockIdx.x * 8 + jl;   // global hidden column

    // ---- stage W tile: 24 rows (3 gates x 8 cols) of 512 floats ----
    for (int i = tid; i < 3072; i += 256) {
        int row = i >> 7;                 // 0..23
        int c   = (i & 127) << 2;         // float offset, step 4
        int g   = row >> 3;
        int jr  = row & 7;
        float4 v = *(const float4*)(a.Whh +
            ((size_t)(g * H_ + blockIdx.x * 8 + jr)) * H_ + c);
        *(float4*)&wsm[row * PH_ + c] = v;
    }

    // ---- stage h_prev (or zeros): 64 rows x 512 floats ----
    if (a.h_prev) {
        for (int i = tid; i < 8192; i += 256) {
            int b = i >> 7;
            int c = (i & 127) << 2;
            float4 v = *(const float4*)(a.h_prev + (size_t)b * H_ + c);
            *(float4*)&hs[b * PH_ + c] = v;
        }
    } else {
        float4 z = make_float4(0.f, 0.f, 0.f, 0.f);
        for (int i = tid; i < 8192; i += 256) {
            int b = i >> 7;
            int c = (i & 127) << 2;
            *(float4*)&hs[b * PH_ + c] = z;
        }
    }
    __syncthreads();

    // ---- packed dot products ----
    uint32_t smem_base = (uint32_t)__cvta_generic_to_shared(sm);
    uint32_t wr_addr = smem_base + (uint32_t)(B_ * PH_ + ( 0 + jl) * PH_) * 4u;
    uint32_t wz_addr = smem_base + (uint32_t)(B_ * PH_ + ( 8 + jl) * PH_) * 4u;
    uint32_t wn_addr = smem_base + (uint32_t)(B_ * PH_ + (16 + jl) * PH_) * 4u;
    uint32_t ha_addr = smem_base + (uint32_t)(b0 * PH_) * 4u;
    uint32_t hb_addr = smem_base + (uint32_t)((b0 + 32) * PH_) * 4u;

    unsigned long long ra = 0ull, za = 0ull, na = 0ull;   // batch b0
    unsigned long long rb = 0ull, zb = 0ull, nb = 0ull;   // batch b0+32

    #pragma unroll 8
    for (int k = 0; k < H_; k += 4) {
        unsigned long long w0, w1, x0, x1, y0, y1, p0, p1, q0, q1;
        uint32_t off = (uint32_t)k * 4u;
        asm("ld.shared.v2.u64 {%0,%1},[%2];" : "=l"(w0), "=l"(w1) : "r"(wr_addr + off));
        asm("ld.shared.v2.u64 {%0,%1},[%2];" : "=l"(x0), "=l"(x1) : "r"(wz_addr + off));
        asm("ld.shared.v2.u64 {%0,%1},[%2];" : "=l"(y0), "=l"(y1) : "r"(wn_addr + off));
        asm("ld.shared.v2.u64 {%0,%1},[%2];" : "=l"(p0), "=l"(p1) : "r"(ha_addr + off));
        asm("ld.shared.v2.u64 {%0,%1},[%2];" : "=l"(q0), "=l"(q1) : "r"(hb_addr + off));
        asm("fma.rn.f32x2 %0,%1,%2,%0;" : "+l"(ra) : "l"(w0), "l"(p0));
        asm("fma.rn.f32x2 %0,%1,%2,%0;" : "+l"(ra) : "l"(w1), "l"(p1));
        asm("fma.rn.f32x2 %0,%1,%2,%0;" : "+l"(za) : "l"(x0), "l"(p0));
        asm("fma.rn.f32x2 %0,%1,%2,%0;" : "+l"(za) : "l"(x1), "l"(p1));
        asm("fma.rn.f32x2 %0,%1,%2,%0;" : "+l"(na) : "l"(y0), "l"(p0));
        asm("fma.rn.f32x2 %0,%1,%2,%0;" : "+l"(na) : "l"(y1), "l"(p1));
        asm("fma.rn.f32x2 %0,%1,%2,%0;" : "+l"(rb) : "l"(w0), "l"(q0));
        asm("fma.rn.f32x2 %0,%1,%2,%0;" : "+l"(rb) : "l"(w1), "l"(q1));
        asm("fma.rn.f32x2 %0,%1,%2,%0;" : "+l"(zb) : "l"(x0), "l"(q0));
        asm("fma.rn.f32x2 %0,%1,%2,%0;" : "+l"(zb) : "l"(x1), "l"(q1));
        asm("fma.rn.f32x2 %0,%1,%2,%0;" : "+l"(nb) : "l"(y0), "l"(q0));
        asm("fma.rn.f32x2 %0,%1,%2,%0;" : "+l"(nb) : "l"(y1), "l"(q1));
    }

    // ---- gates + update for b0 and b0+32 ----
    float brr = a.bhh[jg], bzz = a.bhh[H_ + jg], bnn = a.bhh[2 * H_ + jg];

    #pragma unroll
    for (int q = 0; q < 2; q++) {
        int b = b0 + 32 * q;
        float hr = (q ? pk_lo(rb) + pk_hi(rb) : pk_lo(ra) + pk_hi(ra)) + brr;
        float hz = (q ? pk_lo(zb) + pk_hi(zb) : pk_lo(za) + pk_hi(za)) + bzz;
        float hn = (q ? pk_lo(nb) + pk_hi(nb) : pk_lo(na) + pk_hi(na)) + bnn;
        const float* gi = a.gi_t + (size_t)b * gi_bstride;
        float ir  = gi[jg];
        float iz  = gi[H_ + jg];
        float inn = gi[2 * H_ + jg];
        float r = fast_sigmoid(ir + hr);
        float z = fast_sigmoid(iz + hz);
        float n = tanhf(inn + r * hn);
        float hprev = hs[b * PH_ + jg];
        a.h_out[b * H_ + jg] = (1.0f - z) * n + z * hprev;
    }
}

// ---------------- 5. enc_hidden -> decoder h0 ----------------
__global__ void enc_hidden_kernel(const float* __restrict__ enc_fc_w,
                                  const float* __restrict__ enc_fc_b) {
    int j = blockIdx.x, b = blockIdx.y;
    const float* hp = g_states_pre  + ((size_t)(S_ - 1) * B_ + b) * H_;
    const float* hq = g_states_post + ((size_t)(S_ - 1) * B_ + b) * H_;
    const float* wrow = enc_fc_w + (size_t)j * (2 * H_);
    float acc = 0.f;
    for (int k = threadIdx.x; k < H_; k += 128)
        acc += hp[k] * wrow[k] + hq[k] * wrow[H_ + k];
    acc = blockReduce128(acc);
    if (threadIdx.x == 0) g_dec_h0[b * H_ + j] = tanhf(acc + enc_fc_b[j]);
}

// ---------------- 6. score_enc ----------------
__global__ void score_enc_kernel(const float* __restrict__ out_w) {
    int c = blockIdx.x, b = blockIdx.y;
    int e = c >> 9, t = c & (S_ - 1);
    const float* src = (e ? g_states_post : g_states_pre) + ((size_t)t * B_ + b) * H_;
    float acc = 0.f;
    for (int h = threadIdx.x; h < H_; h += 128)
        acc += fmaxf(src[h], 0.f) * out_w[h];
    acc = blockReduce128(acc);
    if (threadIdx.x == 0) g_score[b * (2 * S_) + c] = acc;
}

// ---------------- 7. hscore ----------------
__global__ void hscore_kernel(const float* __restrict__ out_w, const float* __restrict__ out_b) {
    int t = blockIdx.x, b = blockIdx.y;
    const float* src = g_dstates + ((size_t)t * B_ + b) * H_;
    float acc = 0.f;
    for (int h = threadIdx.x; h < H_; h += 128)
        acc += fmaxf(src[h], 0.f) * out_w[H_ + h];
    acc = blockReduce128(acc);
    if (threadIdx.x == 0) g_hscore[b * T_ + t] = acc + out_b[0];
}

// ---------------- 8. final output: sigmoid fill ----------------
__global__ void output_kernel(float* __restrict__ out) {
    int idx = blockIdx.x * blockDim.x + threadIdx.x;   // < 4194304
    int p  = idx >> 21;
    int r  = idx & ((1 << 21) - 1);
    int b  = r >> 15;
    int r2 = r & 32767;
    int t  = r2 >> 9;
    int s  = r2 & 511;
    float logit = g_score[b * (2 * S_) + p * S_ + s] + g_hscore[b * T_ + t];
    out[idx] = fast_sigmoid(logit);
}

// ---------------- host ----------------
extern "C" void kernel_launch(void* const* d_in, const int* in_sizes, int n_in,
                              void* d_out, int out_size) {
    const int*   pre_seq   = (const int*)  d_in[0];
    const int*   post_seq  = (const int*)  d_in[1];
    const int*   trg       = (const int*)  d_in[2];
    const float* emb       = (const float*)d_in[3];
    const float* pre_Wih   = (const float*)d_in[4];
    const float* pre_Whh   = (const float*)d_in[5];
    const float* pre_bih   = (const float*)d_in[6];
    const float* pre_bhh   = (const float*)d_in[7];
    const float* post_Wih  = (const float*)d_in[8];
    const float* post_Whh  = (const float*)d_in[9];
    const float* post_bih  = (const float*)d_in[10];
    const float* post_bhh  = (const float*)d_in[11];
    const float* enc_fc_w  = (const float*)d_in[12];
    const float* enc_fc_b  = (const float*)d_in[13];
    const float* dec_Wih   = (const float*)d_in[14];
    const float* dec_Whh   = (const float*)d_in[15];
    const float* dec_bih   = (const float*)d_in[16];
    const float* dec_bhh   = (const float*)d_in[17];
    const float* out_w     = (const float*)d_in[18];
    const float* out_b     = (const float*)d_in[19];
    float* out = (float*)d_out;

    float *gi_pre, *gi_post, *gi_dec, *wt_pre, *wt_post, *wt_dec;
    float *st_pre, *st_post, *dst, *dec_h0;
    int* dec_tok;
    cudaGetSymbolAddress((void**)&gi_pre,  g_gi_pre);
    cudaGetSymbolAddress((void**)&gi_post, g_gi_post);
    cudaGetSymbolAddress((void**)&gi_dec,  g_gi_dec);
    cudaGetSymbolAddress((void**)&wt_pre,  g_WT_pre);
    cudaGetSymbolAddress((void**)&wt_post, g_WT_post);
    cudaGetSymbolAddress((void**)&wt_dec,  g_WT_dec);
    cudaGetSymbolAddress((void**)&st_pre,  g_states_pre);
    cudaGetSymbolAddress((void**)&st_post, g_states_post);
    cudaGetSymbolAddress((void**)&dst,     g_dstates);
    cudaGetSymbolAddress((void**)&dec_h0,  g_dec_h0);
    cudaGetSymbolAddress((void**)&dec_tok, g_dec_tokens);

    cudaFuncSetAttribute(gru_step, cudaFuncAttributeMaxDynamicSharedMemorySize, STEP_SMEM);

    dim3 tb(32, 8);
    transpose_k<<<dim3(16, 48), tb>>>(pre_Wih,  wt_pre);
    transpose_k<<<dim3(16, 48), tb>>>(post_Wih, wt_post);
    transpose_k<<<dim3(16, 48), tb>>>(dec_Wih,  wt_dec);

    dec_tokens_kernel<<<16, 256>>>(pre_seq, trg);

    gi_gemm<<<dim3(12, 256), 256>>>(pre_seq,  emb, wt_pre,  pre_bih,  gi_pre);
    gi_gemm<<<dim3(12, 256), 256>>>(post_seq, emb, wt_post, post_bih, gi_post);
    gi_gemm<<<dim3(12, 32),  256>>>(dec_tok,  emb, wt_dec,  dec_bih,  gi_dec);

    // encoder recurrence: 512 steps, both GRUs per launch
    for (int t = 0; t < S_; t++) {
        StepArgs a0, a1;
        a0.h_prev = (t == 0) ? nullptr : st_pre + (size_t)(t - 1) * B_ * H_;
        a0.gi_t   = gi_pre + (size_t)t * G_;
        a0.Whh    = pre_Whh;  a0.bhh = pre_bhh;
        a0.h_out  = st_pre + (size_t)t * B_ * H_;
        a1.h_prev = (t == 0) ? nullptr : st_post + (size_t)(t - 1) * B_ * H_;
        a1.gi_t   = gi_post + (size_t)t * G_;
        a1.Whh    = post_Whh; a1.bhh = post_bhh;
        a1.h_out  = st_post + (size_t)t * B_ * H_;
        gru_step<<<dim3(H_ / 8, 2), 256, STEP_SMEM>>>(a0, a1, S_ * G_);
    }

    enc_hidden_kernel<<<dim3(H_, B_), 128>>>(enc_fc_w, enc_fc_b);
    score_enc_kernel<<<dim3(2 * S_, B_), 128>>>(out_w);

    // decoder recurrence: 64 steps
    for (int t = 0; t < T_; t++) {
        StepArgs a0;
        a0.h_prev = (t == 0) ? dec_h0 : dst + (size_t)(t - 1) * B_ * H_;
        a0.gi_t   = gi_dec + (size_t)t * G_;
        a0.Whh    = dec_Whh;  a0.bhh = dec_bhh;
        a0.h_out  = dst + (size_t)t * B_ * H_;
        gru_step<<<dim3(H_ / 8, 1), 256, STEP_SMEM>>>(a0, a0, T_ * G_);
    }

    hscore_kernel<<<dim3(T_, B_), 128>>>(out_w, out_b);
    output_kernel<<<(2 * B_ * T_ * S_) / 256, 256>>>(out);
}